// round 11
// baseline (speedup 1.0000x reference)
#include <cuda_runtime.h>
#include <cuda_fp16.h>

// Problem constants (fixed by the dataset)
constexpr int NN   = 50000;
constexpr int EE   = 1600000;
constexpr int ET   = EE + NN;     // edges + self loops
constexpr int DIN  = 32;
constexpr int HID  = 64;
constexpr int HEADS= 4;
constexpr int F2   = HEADS * HID; // 256
constexpr int DOUT = 32;
constexpr int NB   = (NN + 255) / 256;   // 196 blocks for scan

// ---------------- scratch (device globals; no allocation allowed) -----------
__device__ __half   g_hx  [NN * HID];  // x @ W_gcn  (half gather table)
__device__ float    g_h1  [NN * HID];  // relu(gcn)
__device__ __half   g_hgh [NN * F2];   // h1 @ W_gat (half gather table)
__device__ __half   g_out2h[NN * F2];  // relu(gat), half
__device__ float    g_as  [NN * HEADS];
__device__ float    g_ad  [NN * HEADS];
__device__ unsigned g_maxenc[2 * HEADS];
__device__ float    g_dinv[NN];
__device__ int      g_deg [NN];
__device__ int      g_rowptr[NN + 1];
__device__ int      g_bsum[NB];
__device__ int      g_pos [EE];        // position of edge within its dst row
__device__ int      g_csr [ET];
__device__ float    g_wgcn[ET];        // GCN edge norm, CSR order
__device__ float    g_wgat[ET * HEADS];// GAT edge weights, CSR order, [edge][head]

// order-preserving float <-> uint encoding for atomicMax
__device__ __forceinline__ unsigned fenc(float f) {
    unsigned b = __float_as_uint(f);
    return (b & 0x80000000u) ? ~b : (b | 0x80000000u);
}
__device__ __forceinline__ float fdec(unsigned u) {
    return (u & 0x80000000u) ? __uint_as_float(u & 0x7fffffffu)
                             : __uint_as_float(~u);
}
__device__ __forceinline__ float lrelu(float e) {
    return (e > 0.f) ? e : 0.2f * e;
}

// ---------------- CSR build -------------------------------------------------
__global__ void init_kernel() {
    int i = blockIdx.x * blockDim.x + threadIdx.x;
    if (i < NN) g_deg[i] = 0;
    if (i < 2 * HEADS) g_maxenc[i] = 0u;
}

__global__ void deg_kernel(const int* __restrict__ ei) {
    int i = blockIdx.x * blockDim.x + threadIdx.x;
    if (i >= EE) return;
    int d = ei[EE + i];
    d = min(max(d, 0), NN - 1);
    g_pos[i] = atomicAdd(&g_deg[d], 1);    // position within row; no 2nd atomic later
}

// block partial sums of (deg+1)
__global__ void scan_partial_kernel() {
    __shared__ int sh[256];
    int t = threadIdx.x, b = blockIdx.x;
    int i = b * 256 + t;
    int v = (i < NN) ? g_deg[i] + 1 : 0;
    sh[t] = v;
    __syncthreads();
#pragma unroll
    for (int off = 128; off > 0; off >>= 1) {
        if (t < off) sh[t] += sh[t + off];
        __syncthreads();
    }
    if (t == 0) g_bsum[b] = sh[0];
}

// rowptr: block offset = reduction of g_bsum[0..b-1], then local scan
__global__ void rowptr_kernel() {
    __shared__ int sh[256];
    __shared__ int boff_sh;
    int t = threadIdx.x, b = blockIdx.x;
    int v0 = (t < b && t < NB) ? g_bsum[t] : 0;
    sh[t] = v0;
    __syncthreads();
#pragma unroll
    for (int off = 128; off > 0; off >>= 1) {
        if (t < off) sh[t] += sh[t + off];
        __syncthreads();
    }
    if (t == 0) boff_sh = sh[0];
    __syncthreads();
    int i = b * 256 + t;
    int v = (i < NN) ? g_deg[i] + 1 : 0;
    sh[t] = v;
    __syncthreads();
    for (int off = 1; off < 256; off <<= 1) {
        int u = (t >= off) ? sh[t - off] : 0;
        __syncthreads();
        sh[t] += u;
        __syncthreads();
    }
    int excl = sh[t] - v + boff_sh;
    if (i < NN) {
        g_rowptr[i] = excl;
        g_dinv[i] = rsqrtf((float)v);
        if (i == NN - 1) g_rowptr[NN] = excl + v;
    }
}

// scatter: edge -> rowptr[dst]+pos ; self-loop at rowptr[dst+1]-1.
// Also writes the GCN edge norm dinv[src]*dinv[dst] in CSR order.
__global__ void csr_fill_kernel(const int* __restrict__ ei) {
    int i = blockIdx.x * blockDim.x + threadIdx.x;
    if (i >= ET) return;
    int src, dst, p;
    if (i < EE) {
        src = min(max(ei[i], 0), NN - 1);
        dst = min(max(ei[EE + i], 0), NN - 1);
        p = g_rowptr[dst] + g_pos[i];
    } else {
        src = i - EE; dst = src;
        p = g_rowptr[dst + 1] - 1;
    }
    g_csr[p]  = src;
    g_wgcn[p] = g_dinv[src] * g_dinv[dst];
}

// ---------------- GEMM 1: hx = x @ W_gcn  (50000x32 @ 32x64), half out ------
__global__ void gemm1_kernel(const float* __restrict__ x,
                             const float* __restrict__ W) {
    __shared__ float Wsh[DIN * HID];        // 8 KB
    for (int i = threadIdx.x; i < DIN * HID; i += blockDim.x) Wsh[i] = W[i];
    __syncthreads();
    int gt   = blockIdx.x * blockDim.x + threadIdx.x;
    int warp = gt >> 5;
    int lane = gt & 31;
    if (warp >= NN) return;
    float xv = x[warp * DIN + lane];
    float a0 = 0.f, a1 = 0.f;
#pragma unroll
    for (int k = 0; k < 32; ++k) {
        float xk = __shfl_sync(0xffffffffu, xv, k);
        a0 += xk * Wsh[k * HID + lane];
        a1 += xk * Wsh[k * HID + 32 + lane];
    }
    g_hx[warp * HID + lane]      = __float2half(a0);
    g_hx[warp * HID + 32 + lane] = __float2half(a1);
}

// ---------------- GCN aggregation: warp per dst; sequential edge weights ----
__global__ void gcn_agg_kernel(const float* __restrict__ b_gcn) {
    int gt   = blockIdx.x * blockDim.x + threadIdx.x;
    int warp = gt >> 5;
    if (warp >= NN) return;
    int lane = gt & 31;
    int beg = g_rowptr[warp], end = g_rowptr[warp + 1];
    float ax = 0.f, ay = 0.f;
    const __half2* hx2 = (const __half2*)g_hx;
    int j = beg;
    for (; j + 2 <= end; j += 2) {
        int s0 = g_csr[j], s1 = g_csr[j + 1];
        float w0 = g_wgcn[j];
        float w1 = g_wgcn[j + 1];
        float2 a = __half22float2(hx2[s0 * 32 + lane]);
        float2 b = __half22float2(hx2[s1 * 32 + lane]);
        ax += a.x * w0 + b.x * w1;
        ay += a.y * w0 + b.y * w1;
    }
    if (j < end) {
        int s0 = g_csr[j];
        float w0 = g_wgcn[j];
        float2 a = __half22float2(hx2[s0 * 32 + lane]);
        ax += a.x * w0;
        ay += a.y * w0;
    }
    float2 o;
    o.x = fmaxf(ax + b_gcn[2 * lane],     0.f);
    o.y = fmaxf(ay + b_gcn[2 * lane + 1], 0.f);
    ((float2*)(g_h1 + (size_t)warp * HID))[lane] = o;
}

// ---------------- GEMM 2 + block-local attention dots (no atomics) ----------
__global__ void gemm2_kernel(const float* __restrict__ Wg,
                             const float* __restrict__ att_src,
                             const float* __restrict__ att_dst) {
    __shared__ float Wsh[64 * 128];         // 32 KB (half the columns)
    __shared__ float rsh[4 * 64];
    __shared__ float ash[128], adh[128];
    __shared__ float red[4][4][2];          // [warp][row][s|d]
    int tid = threadIdx.x;                  // 128
    int colOff = blockIdx.y * 128;
    ash[tid] = att_src[colOff + tid];
    adh[tid] = att_dst[colOff + tid];
    for (int q = tid; q < 64 * 128; q += 128) {
        int k = q >> 7, c = q & 127;
        Wsh[q] = Wg[k * F2 + colOff + c];
    }
    __syncthreads();
    int lane = tid & 31, warp = tid >> 5;
    int rowBase = blockIdx.x * 64;
    for (int r0 = 0; r0 < 64; r0 += 4) {
        for (int q = tid; q < 256; q += 128) {
            int rr = q >> 6, kk = q & 63;
            int row = rowBase + r0 + rr;
            rsh[q] = (row < NN) ? g_h1[(size_t)row * HID + kk] : 0.f;
        }
        __syncthreads();
        float a0 = 0.f, a1 = 0.f, a2 = 0.f, a3 = 0.f;
#pragma unroll
        for (int k = 0; k < 64; ++k) {
            float w = Wsh[k * 128 + tid];
            a0 += rsh[k]       * w;
            a1 += rsh[64 + k]  * w;
            a2 += rsh[128 + k] * w;
            a3 += rsh[192 + k] * w;
        }
        float av[4] = {a0, a1, a2, a3};
#pragma unroll
        for (int rr = 0; rr < 4; ++rr) {
            float vs = av[rr] * ash[tid];
            float vd = av[rr] * adh[tid];
#pragma unroll
            for (int off = 16; off; off >>= 1) {
                vs += __shfl_down_sync(0xffffffffu, vs, off);
                vd += __shfl_down_sync(0xffffffffu, vd, off);
            }
            if (lane == 0) { red[warp][rr][0] = vs; red[warp][rr][1] = vd; }
            int row = rowBase + r0 + rr;
            if (row < NN)
                g_hgh[(size_t)row * F2 + colOff + tid] = __float2half(av[rr]);
        }
        __syncthreads();
        if (tid < 16) {                     // rr(2b) | hl(1b) | sd(1b)
            int rr = tid & 3, hl = (tid >> 2) & 1, sd = tid >> 3;
            int row = rowBase + r0 + rr;
            if (row < NN) {
                float v = red[2 * hl][rr][sd] + red[2 * hl + 1][rr][sd];
                int head = (colOff >> 6) + hl;
                (sd ? g_ad : g_as)[row * HEADS + head] = v;
            }
        }
        __syncthreads();
    }
}

// ---------------- per-head global maxes of a_s and a_d ----------------------
__global__ void maxhead_kernel() {
    __shared__ float shs[256], shd[256];
    int tid = threadIdx.x;
    int i   = blockIdx.x * 256 + tid;
    float vs = -3.0e38f, vd = -3.0e38f;
    if (i < NN * HEADS) { vs = g_as[i]; vd = g_ad[i]; }
    shs[tid] = vs; shd[tid] = vd;
    __syncthreads();
#pragma unroll
    for (int off = 128; off >= 4; off >>= 1) {   // offsets stay multiples of 4
        if (tid < off) {
            shs[tid] = fmaxf(shs[tid], shs[tid + off]);
            shd[tid] = fmaxf(shd[tid], shd[tid + off]);
        }
        __syncthreads();
    }
    if (tid < 4) {
        atomicMax(&g_maxenc[tid],     fenc(shs[tid]));
        atomicMax(&g_maxenc[4 + tid], fenc(shd[tid]));
    }
}

// ---------------- GAT edge weights (CSR order, float4 per edge) -------------
__global__ void edgew_kernel(const int* __restrict__ ei) {
    int i = blockIdx.x * blockDim.x + threadIdx.x;
    if (i >= ET) return;
    int src, dst, p;
    if (i < EE) {
        src = min(max(ei[i], 0), NN - 1);
        dst = min(max(ei[EE + i], 0), NN - 1);
        p = g_rowptr[dst] + g_pos[i];
    } else {
        src = i - EE; dst = src;
        p = g_rowptr[dst + 1] - 1;
    }
    float M0 = lrelu(fdec(g_maxenc[0]) + fdec(g_maxenc[4]));
    float M1 = lrelu(fdec(g_maxenc[1]) + fdec(g_maxenc[5]));
    float M2 = lrelu(fdec(g_maxenc[2]) + fdec(g_maxenc[6]));
    float M3 = lrelu(fdec(g_maxenc[3]) + fdec(g_maxenc[7]));
    float4 as = ((const float4*)g_as)[src];
    float4 ad = ((const float4*)g_ad)[dst];
    float4 w;
    w.x = __expf(lrelu(as.x + ad.x) - M0);
    w.y = __expf(lrelu(as.y + ad.y) - M1);
    w.z = __expf(lrelu(as.z + ad.z) - M2);
    w.w = __expf(lrelu(as.w + ad.w) - M3);
    ((float4*)g_wgat)[p] = w;
}

// ---------------- GAT aggregation: warp per dst, precomputed weights --------
__global__ void gat_agg_kernel(const float* __restrict__ b_gat) {
    int gt   = blockIdx.x * blockDim.x + threadIdx.x;
    int warp = gt >> 5;
    if (warp >= NN) return;
    int lane = gt & 31;
    int hd   = lane >> 3;                   // head for this lane
    int base = hd * HID + (lane & 7) * 8;   // 8 contiguous features
    int beg = g_rowptr[warp], end = g_rowptr[warp + 1];
    float s = 0.f;
    float acc[8];
#pragma unroll
    for (int k = 0; k < 8; ++k) acc[k] = 0.f;

    int j = beg;
    for (; j + 2 <= end; j += 2) {
        int s0 = g_csr[j], s1 = g_csr[j + 1];
        float w0 = g_wgat[j * HEADS + hd];
        float w1 = g_wgat[(j + 1) * HEADS + hd];
        int4 p0 = *(const int4*)(g_hgh + (size_t)s0 * F2 + base);
        int4 p1 = *(const int4*)(g_hgh + (size_t)s1 * F2 + base);
        s += w0 + w1;
        const __half2* h0 = (const __half2*)&p0;
        const __half2* h1 = (const __half2*)&p1;
#pragma unroll
        for (int k = 0; k < 4; ++k) {
            float2 a = __half22float2(h0[k]);
            float2 b = __half22float2(h1[k]);
            acc[2 * k]     += w0 * a.x + w1 * b.x;
            acc[2 * k + 1] += w0 * a.y + w1 * b.y;
        }
    }
    if (j < end) {
        int s0 = g_csr[j];
        float w0 = g_wgat[j * HEADS + hd];
        int4 p0 = *(const int4*)(g_hgh + (size_t)s0 * F2 + base);
        const __half2* h0 = (const __half2*)&p0;
        s += w0;
#pragma unroll
        for (int k = 0; k < 4; ++k) {
            float2 a = __half22float2(h0[k]);
            acc[2 * k]     += w0 * a.x;
            acc[2 * k + 1] += w0 * a.y;
        }
    }
    float inv = 1.f / s;
    __half2* o = (__half2*)(g_out2h + (size_t)warp * F2 + base);
#pragma unroll
    for (int k = 0; k < 4; ++k) {
        float vx = fmaxf(acc[2 * k]     * inv + b_gat[base + 2 * k],     0.f);
        float vy = fmaxf(acc[2 * k + 1] * inv + b_gat[base + 2 * k + 1], 0.f);
        o[k] = __floats2half2_rn(vx, vy);
    }
}

// ---------------- GEMM 3: out = out2h @ W_fc + b_fc (50000x256 @ 256x32) ----
__global__ void gemm3_kernel(const float* __restrict__ Wfc,
                             const float* __restrict__ bfc,
                             float* __restrict__ out) {
    __shared__ float  Wsh[F2 * DOUT];       // 32 KB, layout [k][c]
    __shared__ __half insh[32 * F2];        // 16 KB, 32 rows
    int tid = threadIdx.x;                  // 256
    for (int q = tid; q < F2 * DOUT; q += 256) Wsh[q] = Wfc[q];
    int c  = tid & 31;
    int r4 = tid >> 5;                      // 0..7 -> rows r4*4..r4*4+3
    float bv = bfc[c];
    int rowBase = blockIdx.x * 128;
    for (int g = 0; g < 128; g += 32) {
        __syncthreads();
        for (int q = tid; q < 32 * 128; q += 256) {
            int rr = q >> 7, kk2 = q & 127;
            int row = rowBase + g + rr;
            ((__half2*)insh)[q] = (row < NN)
                ? ((const __half2*)(g_out2h + (size_t)row * F2))[kk2]
                : __floats2half2_rn(0.f, 0.f);
        }
        __syncthreads();
        float acc0 = 0.f, acc1 = 0.f, acc2 = 0.f, acc3 = 0.f;
        const uint2* in0 = (const uint2*)(insh + (r4 * 4 + 0) * F2);
        const uint2* in1 = (const uint2*)(insh + (r4 * 4 + 1) * F2);
        const uint2* in2 = (const uint2*)(insh + (r4 * 4 + 2) * F2);
        const uint2* in3 = (const uint2*)(insh + (r4 * 4 + 3) * F2);
#pragma unroll 8
        for (int k4 = 0; k4 < 64; ++k4) {
            uint2 u0 = in0[k4], u1 = in1[k4], u2 = in2[k4], u3 = in3[k4];
            float w0 = Wsh[(4 * k4 + 0) * DOUT + c];
            float w1 = Wsh[(4 * k4 + 1) * DOUT + c];
            float w2 = Wsh[(4 * k4 + 2) * DOUT + c];
            float w3 = Wsh[(4 * k4 + 3) * DOUT + c];
            float2 a0 = __half22float2(*(const __half2*)&u0.x);
            float2 b0 = __half22float2(*(const __half2*)&u0.y);
            float2 a1 = __half22float2(*(const __half2*)&u1.x);
            float2 b1 = __half22float2(*(const __half2*)&u1.y);
            float2 a2 = __half22float2(*(const __half2*)&u2.x);
            float2 b2 = __half22float2(*(const __half2*)&u2.y);
            float2 a3 = __half22float2(*(const __half2*)&u3.x);
            float2 b3 = __half22float2(*(const __half2*)&u3.y);
            acc0 += a0.x * w0 + a0.y * w1 + b0.x * w2 + b0.y * w3;
            acc1 += a1.x * w0 + a1.y * w1 + b1.x * w2 + b1.y * w3;
            acc2 += a2.x * w0 + a2.y * w1 + b2.x * w2 + b2.y * w3;
            acc3 += a3.x * w0 + a3.y * w1 + b3.x * w2 + b3.y * w3;
        }
        int row = rowBase + g + r4 * 4;
        if (row     < NN) out[(row    ) * DOUT + c] = acc0 + bv;
        if (row + 1 < NN) out[(row + 1) * DOUT + c] = acc1 + bv;
        if (row + 2 < NN) out[(row + 2) * DOUT + c] = acc2 + bv;
        if (row + 3 < NN) out[(row + 3) * DOUT + c] = acc3 + bv;
    }
}

// ---------------- launch ----------------------------------------------------
extern "C" void kernel_launch(void* const* d_in, const int* in_sizes, int n_in,
                              void* d_out, int out_size) {
    const float* x       = (const float*)d_in[0];
    const int*   ei      = (const int*)  d_in[1];   // int32 (JAX x64 off)
    const float* W_gcn   = (const float*)d_in[2];
    const float* b_gcn   = (const float*)d_in[3];
    const float* W_gat   = (const float*)d_in[4];
    const float* att_src = (const float*)d_in[5];
    const float* att_dst = (const float*)d_in[6];
    const float* b_gat   = (const float*)d_in[7];
    const float* W_fc    = (const float*)d_in[8];
    const float* b_fc    = (const float*)d_in[9];
    float*       out     = (float*)d_out;

    init_kernel        <<<(NN + 255) / 256, 256>>>();
    deg_kernel         <<<(EE + 255) / 256, 256>>>(ei);
    scan_partial_kernel<<<NB, 256>>>();
    rowptr_kernel      <<<NB, 256>>>();
    csr_fill_kernel    <<<(ET + 255) / 256, 256>>>(ei);

    gemm1_kernel       <<<(NN * 32 + 255) / 256, 256>>>(x, W_gcn);
    gcn_agg_kernel     <<<(NN * 32 + 255) / 256, 256>>>(b_gcn);

    gemm2_kernel       <<<dim3((NN + 63) / 64, 2), 128>>>(W_gat, att_src, att_dst);
    maxhead_kernel     <<<(NN * HEADS + 255) / 256, 256>>>();
    edgew_kernel       <<<(ET + 255) / 256, 256>>>(ei);
    gat_agg_kernel     <<<(NN * 32 + 255) / 256, 256>>>(b_gat);

    gemm3_kernel       <<<(NN + 127) / 128, 256>>>(W_fc, b_fc, out);
}

// round 12
// speedup vs baseline: 1.0042x; 1.0042x over previous
#include <cuda_runtime.h>
#include <cuda_fp16.h>

// Problem constants (fixed by the dataset)
constexpr int NN   = 50000;
constexpr int EE   = 1600000;
constexpr int ET   = EE + NN;     // edges + self loops
constexpr int DIN  = 32;
constexpr int HID  = 64;
constexpr int HEADS= 4;
constexpr int F2   = HEADS * HID; // 256
constexpr int DOUT = 32;
constexpr int NB   = (NN + 255) / 256;   // 196 blocks for scan

// ---------------- scratch (device globals; no allocation allowed) -----------
__device__ __half   g_hx  [NN * HID];  // x @ W_gcn  (half gather table)
__device__ float    g_h1  [NN * HID];  // relu(gcn)
__device__ __half   g_hgh [NN * F2];   // h1 @ W_gat (half gather table)
__device__ __half   g_out2h[NN * F2];  // relu(gat), half
__device__ float    g_as  [NN * HEADS];
__device__ float    g_ad  [NN * HEADS];
__device__ unsigned g_maxenc[2 * HEADS];
__device__ float    g_dinv[NN];
__device__ int      g_deg [NN];
__device__ int      g_rowptr[NN + 1];
__device__ int      g_bsum[NB];
__device__ int      g_pos [EE];        // position of edge within its dst row
__device__ int      g_csr [ET];
__device__ float    g_wgcn[ET];        // GCN edge norm, CSR order
__device__ float    g_wgat[ET * HEADS];// GAT edge weights, CSR order, [edge][head]

// order-preserving float <-> uint encoding for atomicMax
__device__ __forceinline__ unsigned fenc(float f) {
    unsigned b = __float_as_uint(f);
    return (b & 0x80000000u) ? ~b : (b | 0x80000000u);
}
__device__ __forceinline__ float fdec(unsigned u) {
    return (u & 0x80000000u) ? __uint_as_float(u & 0x7fffffffu)
                             : __uint_as_float(~u);
}
__device__ __forceinline__ float lrelu(float e) {
    return (e > 0.f) ? e : 0.2f * e;
}

// ---------------- CSR build -------------------------------------------------
__global__ void init_kernel() {
    int i = blockIdx.x * blockDim.x + threadIdx.x;
    if (i < NN) g_deg[i] = 0;
    if (i < 2 * HEADS) g_maxenc[i] = 0u;
}

__global__ void deg_kernel(const int* __restrict__ ei) {
    int i = blockIdx.x * blockDim.x + threadIdx.x;
    if (i >= EE) return;
    int d = ei[EE + i];
    d = min(max(d, 0), NN - 1);
    g_pos[i] = atomicAdd(&g_deg[d], 1);    // position within row; no 2nd atomic later
}

// block partial sums of (deg+1)
__global__ void scan_partial_kernel() {
    __shared__ int sh[256];
    int t = threadIdx.x, b = blockIdx.x;
    int i = b * 256 + t;
    int v = (i < NN) ? g_deg[i] + 1 : 0;
    sh[t] = v;
    __syncthreads();
#pragma unroll
    for (int off = 128; off > 0; off >>= 1) {
        if (t < off) sh[t] += sh[t + off];
        __syncthreads();
    }
    if (t == 0) g_bsum[b] = sh[0];
}

// rowptr: block offset = reduction of g_bsum[0..b-1], then local scan
__global__ void rowptr_kernel() {
    __shared__ int sh[256];
    __shared__ int boff_sh;
    int t = threadIdx.x, b = blockIdx.x;
    int v0 = (t < b && t < NB) ? g_bsum[t] : 0;
    sh[t] = v0;
    __syncthreads();
#pragma unroll
    for (int off = 128; off > 0; off >>= 1) {
        if (t < off) sh[t] += sh[t + off];
        __syncthreads();
    }
    if (t == 0) boff_sh = sh[0];
    __syncthreads();
    int i = b * 256 + t;
    int v = (i < NN) ? g_deg[i] + 1 : 0;
    sh[t] = v;
    __syncthreads();
    for (int off = 1; off < 256; off <<= 1) {
        int u = (t >= off) ? sh[t - off] : 0;
        __syncthreads();
        sh[t] += u;
        __syncthreads();
    }
    int excl = sh[t] - v + boff_sh;
    if (i < NN) {
        g_rowptr[i] = excl;
        g_dinv[i] = rsqrtf((float)v);
        if (i == NN - 1) g_rowptr[NN] = excl + v;
    }
}

// scatter: edge -> rowptr[dst]+pos ; self-loop at rowptr[dst+1]-1.
// Also writes the GCN edge norm dinv[src]*dinv[dst] in CSR order.
__global__ void csr_fill_kernel(const int* __restrict__ ei) {
    int i = blockIdx.x * blockDim.x + threadIdx.x;
    if (i >= ET) return;
    int src, dst, p;
    if (i < EE) {
        src = min(max(ei[i], 0), NN - 1);
        dst = min(max(ei[EE + i], 0), NN - 1);
        p = g_rowptr[dst] + g_pos[i];
    } else {
        src = i - EE; dst = src;
        p = g_rowptr[dst + 1] - 1;
    }
    g_csr[p]  = src;
    g_wgcn[p] = g_dinv[src] * g_dinv[dst];
}

// ---------------- GEMM 1: hx = x @ W_gcn  (50000x32 @ 32x64), half out ------
__global__ void gemm1_kernel(const float* __restrict__ x,
                             const float* __restrict__ W) {
    __shared__ float Wsh[DIN * HID];        // 8 KB
    for (int i = threadIdx.x; i < DIN * HID; i += blockDim.x) Wsh[i] = W[i];
    __syncthreads();
    int gt   = blockIdx.x * blockDim.x + threadIdx.x;
    int warp = gt >> 5;
    int lane = gt & 31;
    if (warp >= NN) return;
    float xv = x[warp * DIN + lane];
    float a0 = 0.f, a1 = 0.f;
#pragma unroll
    for (int k = 0; k < 32; ++k) {
        float xk = __shfl_sync(0xffffffffu, xv, k);
        a0 += xk * Wsh[k * HID + lane];
        a1 += xk * Wsh[k * HID + 32 + lane];
    }
    g_hx[warp * HID + lane]      = __float2half(a0);
    g_hx[warp * HID + 32 + lane] = __float2half(a1);
}

// ---------------- GCN aggregation: warp per dst; sequential edge weights ----
__global__ void gcn_agg_kernel(const float* __restrict__ b_gcn) {
    int gt   = blockIdx.x * blockDim.x + threadIdx.x;
    int warp = gt >> 5;
    if (warp >= NN) return;
    int lane = gt & 31;
    int beg = g_rowptr[warp], end = g_rowptr[warp + 1];
    float ax = 0.f, ay = 0.f;
    const __half2* hx2 = (const __half2*)g_hx;
    int j = beg;
    for (; j + 2 <= end; j += 2) {
        int s0 = g_csr[j], s1 = g_csr[j + 1];
        float w0 = g_wgcn[j];
        float w1 = g_wgcn[j + 1];
        float2 a = __half22float2(hx2[s0 * 32 + lane]);
        float2 b = __half22float2(hx2[s1 * 32 + lane]);
        ax += a.x * w0 + b.x * w1;
        ay += a.y * w0 + b.y * w1;
    }
    if (j < end) {
        int s0 = g_csr[j];
        float w0 = g_wgcn[j];
        float2 a = __half22float2(hx2[s0 * 32 + lane]);
        ax += a.x * w0;
        ay += a.y * w0;
    }
    float2 o;
    o.x = fmaxf(ax + b_gcn[2 * lane],     0.f);
    o.y = fmaxf(ay + b_gcn[2 * lane + 1], 0.f);
    ((float2*)(g_h1 + (size_t)warp * HID))[lane] = o;
}

// ---------------- GEMM 2 + block-local attention dots (no atomics) ----------
__global__ void gemm2_kernel(const float* __restrict__ Wg,
                             const float* __restrict__ att_src,
                             const float* __restrict__ att_dst) {
    __shared__ float Wsh[64 * 128];         // 32 KB (half the columns)
    __shared__ float rsh[4 * 64];
    __shared__ float ash[128], adh[128];
    __shared__ float red[4][4][2];          // [warp][row][s|d]
    int tid = threadIdx.x;                  // 128
    int colOff = blockIdx.y * 128;
    ash[tid] = att_src[colOff + tid];
    adh[tid] = att_dst[colOff + tid];
    for (int q = tid; q < 64 * 128; q += 128) {
        int k = q >> 7, c = q & 127;
        Wsh[q] = Wg[k * F2 + colOff + c];
    }
    __syncthreads();
    int lane = tid & 31, warp = tid >> 5;
    int rowBase = blockIdx.x * 64;
    for (int r0 = 0; r0 < 64; r0 += 4) {
        for (int q = tid; q < 256; q += 128) {
            int rr = q >> 6, kk = q & 63;
            int row = rowBase + r0 + rr;
            rsh[q] = (row < NN) ? g_h1[(size_t)row * HID + kk] : 0.f;
        }
        __syncthreads();
        float a0 = 0.f, a1 = 0.f, a2 = 0.f, a3 = 0.f;
#pragma unroll
        for (int k = 0; k < 64; ++k) {
            float w = Wsh[k * 128 + tid];
            a0 += rsh[k]       * w;
            a1 += rsh[64 + k]  * w;
            a2 += rsh[128 + k] * w;
            a3 += rsh[192 + k] * w;
        }
        float av[4] = {a0, a1, a2, a3};
#pragma unroll
        for (int rr = 0; rr < 4; ++rr) {
            float vs = av[rr] * ash[tid];
            float vd = av[rr] * adh[tid];
#pragma unroll
            for (int off = 16; off; off >>= 1) {
                vs += __shfl_down_sync(0xffffffffu, vs, off);
                vd += __shfl_down_sync(0xffffffffu, vd, off);
            }
            if (lane == 0) { red[warp][rr][0] = vs; red[warp][rr][1] = vd; }
            int row = rowBase + r0 + rr;
            if (row < NN)
                g_hgh[(size_t)row * F2 + colOff + tid] = __float2half(av[rr]);
        }
        __syncthreads();
        if (tid < 16) {                     // rr(2b) | hl(1b) | sd(1b)
            int rr = tid & 3, hl = (tid >> 2) & 1, sd = tid >> 3;
            int row = rowBase + r0 + rr;
            if (row < NN) {
                float v = red[2 * hl][rr][sd] + red[2 * hl + 1][rr][sd];
                int head = (colOff >> 6) + hl;
                (sd ? g_ad : g_as)[row * HEADS + head] = v;
            }
        }
        __syncthreads();
    }
}

// ---------------- per-head global maxes of a_s and a_d ----------------------
__global__ void maxhead_kernel() {
    __shared__ float shs[256], shd[256];
    int tid = threadIdx.x;
    int i   = blockIdx.x * 256 + tid;
    float vs = -3.0e38f, vd = -3.0e38f;
    if (i < NN * HEADS) { vs = g_as[i]; vd = g_ad[i]; }
    shs[tid] = vs; shd[tid] = vd;
    __syncthreads();
#pragma unroll
    for (int off = 128; off >= 4; off >>= 1) {   // offsets stay multiples of 4
        if (tid < off) {
            shs[tid] = fmaxf(shs[tid], shs[tid + off]);
            shd[tid] = fmaxf(shd[tid], shd[tid + off]);
        }
        __syncthreads();
    }
    if (tid < 4) {
        atomicMax(&g_maxenc[tid],     fenc(shs[tid]));
        atomicMax(&g_maxenc[4 + tid], fenc(shd[tid]));
    }
}

// ---------------- GAT edge weights (CSR order, float4 per edge) -------------
__global__ void edgew_kernel(const int* __restrict__ ei) {
    int i = blockIdx.x * blockDim.x + threadIdx.x;
    if (i >= ET) return;
    int src, dst, p;
    if (i < EE) {
        src = min(max(ei[i], 0), NN - 1);
        dst = min(max(ei[EE + i], 0), NN - 1);
        p = g_rowptr[dst] + g_pos[i];
    } else {
        src = i - EE; dst = src;
        p = g_rowptr[dst + 1] - 1;
    }
    float M0 = lrelu(fdec(g_maxenc[0]) + fdec(g_maxenc[4]));
    float M1 = lrelu(fdec(g_maxenc[1]) + fdec(g_maxenc[5]));
    float M2 = lrelu(fdec(g_maxenc[2]) + fdec(g_maxenc[6]));
    float M3 = lrelu(fdec(g_maxenc[3]) + fdec(g_maxenc[7]));
    float4 as = ((const float4*)g_as)[src];
    float4 ad = ((const float4*)g_ad)[dst];
    float4 w;
    w.x = __expf(lrelu(as.x + ad.x) - M0);
    w.y = __expf(lrelu(as.y + ad.y) - M1);
    w.z = __expf(lrelu(as.z + ad.z) - M2);
    w.w = __expf(lrelu(as.w + ad.w) - M3);
    ((float4*)g_wgat)[p] = w;
}

// ---------------- GAT aggregation: warp per dst, precomputed weights --------
__global__ void gat_agg_kernel(const float* __restrict__ b_gat) {
    int gt   = blockIdx.x * blockDim.x + threadIdx.x;
    int warp = gt >> 5;
    if (warp >= NN) return;
    int lane = gt & 31;
    int hd   = lane >> 3;                   // head for this lane
    int base = hd * HID + (lane & 7) * 8;   // 8 contiguous features
    int beg = g_rowptr[warp], end = g_rowptr[warp + 1];
    float s = 0.f;
    float acc[8];
#pragma unroll
    for (int k = 0; k < 8; ++k) acc[k] = 0.f;

    int j = beg;
    for (; j + 2 <= end; j += 2) {
        int s0 = g_csr[j], s1 = g_csr[j + 1];
        float w0 = g_wgat[j * HEADS + hd];
        float w1 = g_wgat[(j + 1) * HEADS + hd];
        int4 p0 = *(const int4*)(g_hgh + (size_t)s0 * F2 + base);
        int4 p1 = *(const int4*)(g_hgh + (size_t)s1 * F2 + base);
        s += w0 + w1;
        const __half2* h0 = (const __half2*)&p0;
        const __half2* h1 = (const __half2*)&p1;
#pragma unroll
        for (int k = 0; k < 4; ++k) {
            float2 a = __half22float2(h0[k]);
            float2 b = __half22float2(h1[k]);
            acc[2 * k]     += w0 * a.x + w1 * b.x;
            acc[2 * k + 1] += w0 * a.y + w1 * b.y;
        }
    }
    if (j < end) {
        int s0 = g_csr[j];
        float w0 = g_wgat[j * HEADS + hd];
        int4 p0 = *(const int4*)(g_hgh + (size_t)s0 * F2 + base);
        const __half2* h0 = (const __half2*)&p0;
        s += w0;
#pragma unroll
        for (int k = 0; k < 4; ++k) {
            float2 a = __half22float2(h0[k]);
            acc[2 * k]     += w0 * a.x;
            acc[2 * k + 1] += w0 * a.y;
        }
    }
    float inv = 1.f / s;
    __half2* o = (__half2*)(g_out2h + (size_t)warp * F2 + base);
#pragma unroll
    for (int k = 0; k < 4; ++k) {
        float vx = fmaxf(acc[2 * k]     * inv + b_gat[base + 2 * k],     0.f);
        float vy = fmaxf(acc[2 * k + 1] * inv + b_gat[base + 2 * k + 1], 0.f);
        o[k] = __floats2half2_rn(vx, vy);
    }
}

// ---------------- GEMM 3: out = out2h @ W_fc + b_fc (50000x256 @ 256x32) ----
__global__ void gemm3_kernel(const float* __restrict__ Wfc,
                             const float* __restrict__ bfc,
                             float* __restrict__ out) {
    __shared__ float  Wsh[F2 * DOUT];       // 32 KB, layout [k][c]
    __shared__ __half insh[32 * F2];        // 16 KB, 32 rows
    int tid = threadIdx.x;                  // 256
    for (int q = tid; q < F2 * DOUT; q += 256) Wsh[q] = Wfc[q];
    int c  = tid & 31;
    int r4 = tid >> 5;                      // 0..7 -> rows r4*4..r4*4+3
    float bv = bfc[c];
    int rowBase = blockIdx.x * 128;
    for (int g = 0; g < 128; g += 32) {
        __syncthreads();
        for (int q = tid; q < 32 * 128; q += 256) {
            int rr = q >> 7, kk2 = q & 127;
            int row = rowBase + g + rr;
            ((__half2*)insh)[q] = (row < NN)
                ? ((const __half2*)(g_out2h + (size_t)row * F2))[kk2]
                : __floats2half2_rn(0.f, 0.f);
        }
        __syncthreads();
        float acc0 = 0.f, acc1 = 0.f, acc2 = 0.f, acc3 = 0.f;
        const uint2* in0 = (const uint2*)(insh + (r4 * 4 + 0) * F2);
        const uint2* in1 = (const uint2*)(insh + (r4 * 4 + 1) * F2);
        const uint2* in2 = (const uint2*)(insh + (r4 * 4 + 2) * F2);
        const uint2* in3 = (const uint2*)(insh + (r4 * 4 + 3) * F2);
#pragma unroll 8
        for (int k4 = 0; k4 < 64; ++k4) {
            uint2 u0 = in0[k4], u1 = in1[k4], u2 = in2[k4], u3 = in3[k4];
            float w0 = Wsh[(4 * k4 + 0) * DOUT + c];
            float w1 = Wsh[(4 * k4 + 1) * DOUT + c];
            float w2 = Wsh[(4 * k4 + 2) * DOUT + c];
            float w3 = Wsh[(4 * k4 + 3) * DOUT + c];
            float2 a0 = __half22float2(*(const __half2*)&u0.x);
            float2 b0 = __half22float2(*(const __half2*)&u0.y);
            float2 a1 = __half22float2(*(const __half2*)&u1.x);
            float2 b1 = __half22float2(*(const __half2*)&u1.y);
            float2 a2 = __half22float2(*(const __half2*)&u2.x);
            float2 b2 = __half22float2(*(const __half2*)&u2.y);
            float2 a3 = __half22float2(*(const __half2*)&u3.x);
            float2 b3 = __half22float2(*(const __half2*)&u3.y);
            acc0 += a0.x * w0 + a0.y * w1 + b0.x * w2 + b0.y * w3;
            acc1 += a1.x * w0 + a1.y * w1 + b1.x * w2 + b1.y * w3;
            acc2 += a2.x * w0 + a2.y * w1 + b2.x * w2 + b2.y * w3;
            acc3 += a3.x * w0 + a3.y * w1 + b3.x * w2 + b3.y * w3;
        }
        int row = rowBase + g + r4 * 4;
        if (row     < NN) out[(row    ) * DOUT + c] = acc0 + bv;
        if (row + 1 < NN) out[(row + 1) * DOUT + c] = acc1 + bv;
        if (row + 2 < NN) out[(row + 2) * DOUT + c] = acc2 + bv;
        if (row + 3 < NN) out[(row + 3) * DOUT + c] = acc3 + bv;
    }
}

// ---------------- launch ----------------------------------------------------
extern "C" void kernel_launch(void* const* d_in, const int* in_sizes, int n_in,
                              void* d_out, int out_size) {
    const float* x       = (const float*)d_in[0];
    const int*   ei      = (const int*)  d_in[1];   // int32 (JAX x64 off)
    const float* W_gcn   = (const float*)d_in[2];
    const float* b_gcn   = (const float*)d_in[3];
    const float* W_gat   = (const float*)d_in[4];
    const float* att_src = (const float*)d_in[5];
    const float* att_dst = (const float*)d_in[6];
    const float* b_gat   = (const float*)d_in[7];
    const float* W_fc    = (const float*)d_in[8];
    const float* b_fc    = (const float*)d_in[9];
    float*       out     = (float*)d_out;

    init_kernel        <<<(NN + 255) / 256, 256>>>();
    deg_kernel         <<<(EE + 255) / 256, 256>>>(ei);
    scan_partial_kernel<<<NB, 256>>>();
    rowptr_kernel      <<<NB, 256>>>();
    csr_fill_kernel    <<<(ET + 255) / 256, 256>>>(ei);

    gemm1_kernel       <<<(NN * 32 + 255) / 256, 256>>>(x, W_gcn);
    gcn_agg_kernel     <<<(NN * 32 + 255) / 256, 256>>>(b_gcn);

    gemm2_kernel       <<<dim3((NN + 63) / 64, 2), 128>>>(W_gat, att_src, att_dst);
    maxhead_kernel     <<<(NN * HEADS + 255) / 256, 256>>>();
    edgew_kernel       <<<(ET + 255) / 256, 256>>>(ei);
    gat_agg_kernel     <<<(NN * 32 + 255) / 256, 256>>>(b_gat);

    gemm3_kernel       <<<(NN + 127) / 128, 256>>>(W_fc, b_fc, out);
}

// round 14
// speedup vs baseline: 1.0639x; 1.0595x over previous
#include <cuda_runtime.h>
#include <cuda_fp16.h>

// Problem constants (fixed by the dataset)
constexpr int NN   = 50000;
constexpr int EE   = 1600000;
constexpr int ET   = EE + NN;     // edges + self loops
constexpr int DIN  = 32;
constexpr int HID  = 64;
constexpr int HEADS= 4;
constexpr int F2   = HEADS * HID; // 256
constexpr int DOUT = 32;
constexpr int NB   = (NN + 255) / 256;   // 196 blocks for scan

// ---------------- scratch (device globals; no allocation allowed) -----------
__device__ __half g_hx  [NN * HID];  // x @ W_gcn  (half gather table)
__device__ float  g_h1  [NN * HID];  // relu(gcn)
__device__ __half g_hgh [NN * F2];   // h1 @ W_gat (half gather table)
__device__ __half g_out2h[NN * F2];  // relu(gat), half
__device__ float  g_as  [NN * HEADS];
__device__ float  g_ad  [NN * HEADS];
__device__ float  g_dinv[NN];
__device__ int    g_deg [NN];
__device__ int    g_rowptr[NN + 1];
__device__ int    g_bsum[NB];
__device__ int    g_pos [EE];        // position of edge within its dst row
__device__ int    g_csr [ET];

// ---------------- CSR build -------------------------------------------------
__global__ void init_kernel() {
    int i = blockIdx.x * blockDim.x + threadIdx.x;
    if (i < NN) g_deg[i] = 0;
}

__global__ void deg_kernel(const int* __restrict__ ei) {
    int i = blockIdx.x * blockDim.x + threadIdx.x;
    if (i >= EE) return;
    int d = ei[EE + i];
    d = min(max(d, 0), NN - 1);
    g_pos[i] = atomicAdd(&g_deg[d], 1);    // position within row; no 2nd atomic later
}

// block partial sums of (deg+1)
__global__ void scan_partial_kernel() {
    __shared__ int sh[256];
    int t = threadIdx.x, b = blockIdx.x;
    int i = b * 256 + t;
    int v = (i < NN) ? g_deg[i] + 1 : 0;
    sh[t] = v;
    __syncthreads();
#pragma unroll
    for (int off = 128; off > 0; off >>= 1) {
        if (t < off) sh[t] += sh[t + off];
        __syncthreads();
    }
    if (t == 0) g_bsum[b] = sh[0];
}

// rowptr: block offset = reduction of g_bsum[0..b-1], then local scan
__global__ void rowptr_kernel() {
    __shared__ int sh[256];
    __shared__ int boff_sh;
    int t = threadIdx.x, b = blockIdx.x;
    int v0 = (t < b && t < NB) ? g_bsum[t] : 0;
    sh[t] = v0;
    __syncthreads();
#pragma unroll
    for (int off = 128; off > 0; off >>= 1) {
        if (t < off) sh[t] += sh[t + off];
        __syncthreads();
    }
    if (t == 0) boff_sh = sh[0];
    __syncthreads();
    int i = b * 256 + t;
    int v = (i < NN) ? g_deg[i] + 1 : 0;
    sh[t] = v;
    __syncthreads();
    for (int off = 1; off < 256; off <<= 1) {
        int u = (t >= off) ? sh[t - off] : 0;
        __syncthreads();
        sh[t] += u;
        __syncthreads();
    }
    int excl = sh[t] - v + boff_sh;
    if (i < NN) {
        g_rowptr[i] = excl;
        g_dinv[i] = rsqrtf((float)v);
        if (i == NN - 1) g_rowptr[NN] = excl + v;
    }
}

// plain scatter: edge -> rowptr[dst]+pos ; self-loop at rowptr[dst+1]-1
__global__ void csr_fill_kernel(const int* __restrict__ ei) {
    int i = blockIdx.x * blockDim.x + threadIdx.x;
    if (i >= ET) return;
    if (i < EE) {
        int src = min(max(ei[i], 0), NN - 1);
        int dst = min(max(ei[EE + i], 0), NN - 1);
        g_csr[g_rowptr[dst] + g_pos[i]] = src;
    } else {
        int node = i - EE;
        g_csr[g_rowptr[node + 1] - 1] = node;
    }
}

// ---------------- GEMM 1: hx = x @ W_gcn  (50000x32 @ 32x64), half out ------
__global__ void gemm1_kernel(const float* __restrict__ x,
                             const float* __restrict__ W) {
    __shared__ float Wsh[DIN * HID];        // 8 KB
    for (int i = threadIdx.x; i < DIN * HID; i += blockDim.x) Wsh[i] = W[i];
    __syncthreads();
    int gt   = blockIdx.x * blockDim.x + threadIdx.x;
    int warp = gt >> 5;
    int lane = gt & 31;
    if (warp >= NN) return;
    float xv = x[warp * DIN + lane];
    float a0 = 0.f, a1 = 0.f;
#pragma unroll
    for (int k = 0; k < 32; ++k) {
        float xk = __shfl_sync(0xffffffffu, xv, k);
        a0 += xk * Wsh[k * HID + lane];
        a1 += xk * Wsh[k * HID + 32 + lane];
    }
    g_hx[warp * HID + lane]      = __float2half(a0);
    g_hx[warp * HID + 32 + lane] = __float2half(a1);
}

// ---------------- GCN aggregation: warp per dst, half gathers, unroll 2 -----
__global__ void gcn_agg_kernel(const float* __restrict__ b_gcn) {
    int gt   = blockIdx.x * blockDim.x + threadIdx.x;
    int warp = gt >> 5;
    if (warp >= NN) return;
    int lane = gt & 31;
    int beg = g_rowptr[warp], end = g_rowptr[warp + 1];
    float dd = g_dinv[warp];
    float ax = 0.f, ay = 0.f;
    const __half2* hx2 = (const __half2*)g_hx;
    int j = beg;
    for (; j + 2 <= end; j += 2) {
        int s0 = g_csr[j], s1 = g_csr[j + 1];
        float w0 = g_dinv[s0] * dd;
        float w1 = g_dinv[s1] * dd;
        float2 a = __half22float2(hx2[s0 * 32 + lane]);
        float2 b = __half22float2(hx2[s1 * 32 + lane]);
        ax += a.x * w0 + b.x * w1;
        ay += a.y * w0 + b.y * w1;
    }
    if (j < end) {
        int s0 = g_csr[j];
        float w0 = g_dinv[s0] * dd;
        float2 a = __half22float2(hx2[s0 * 32 + lane]);
        ax += a.x * w0;
        ay += a.y * w0;
    }
    float2 o;
    o.x = fmaxf(ax + b_gcn[2 * lane],     0.f);
    o.y = fmaxf(ay + b_gcn[2 * lane + 1], 0.f);
    ((float2*)(g_h1 + (size_t)warp * HID))[lane] = o;
}

// ---------------- GEMM 2 + block-local attention dots (no atomics) ----------
// Register-tiled inner loop: float4 loads of rsh (same accumulation order).
__global__ void gemm2_kernel(const float* __restrict__ Wg,
                             const float* __restrict__ att_src,
                             const float* __restrict__ att_dst) {
    __shared__ float Wsh[64 * 128];         // 32 KB (half the columns)
    __shared__ float rsh[4 * 64];
    __shared__ float ash[128], adh[128];
    __shared__ float red[4][4][2];          // [warp][row][s|d]
    int tid = threadIdx.x;                  // 128
    int colOff = blockIdx.y * 128;
    ash[tid] = att_src[colOff + tid];
    adh[tid] = att_dst[colOff + tid];
    for (int q = tid; q < 64 * 128; q += 128) {
        int k = q >> 7, c = q & 127;
        Wsh[q] = Wg[k * F2 + colOff + c];
    }
    __syncthreads();
    int lane = tid & 31, warp = tid >> 5;
    int rowBase = blockIdx.x * 64;
    for (int r0 = 0; r0 < 64; r0 += 4) {
        for (int q = tid; q < 256; q += 128) {
            int rr = q >> 6, kk = q & 63;
            int row = rowBase + r0 + rr;
            rsh[q] = (row < NN) ? g_h1[(size_t)row * HID + kk] : 0.f;
        }
        __syncthreads();
        float a0 = 0.f, a1 = 0.f, a2 = 0.f, a3 = 0.f;
#pragma unroll
        for (int k4 = 0; k4 < 16; ++k4) {
            float4 r0v = *(const float4*)&rsh[        4 * k4];
            float4 r1v = *(const float4*)&rsh[ 64 +   4 * k4];
            float4 r2v = *(const float4*)&rsh[128 +   4 * k4];
            float4 r3v = *(const float4*)&rsh[192 +   4 * k4];
            float w0 = Wsh[(4 * k4 + 0) * 128 + tid];
            float w1 = Wsh[(4 * k4 + 1) * 128 + tid];
            float w2 = Wsh[(4 * k4 + 2) * 128 + tid];
            float w3 = Wsh[(4 * k4 + 3) * 128 + tid];
            a0 += r0v.x * w0; a0 += r0v.y * w1; a0 += r0v.z * w2; a0 += r0v.w * w3;
            a1 += r1v.x * w0; a1 += r1v.y * w1; a1 += r1v.z * w2; a1 += r1v.w * w3;
            a2 += r2v.x * w0; a2 += r2v.y * w1; a2 += r2v.z * w2; a2 += r2v.w * w3;
            a3 += r3v.x * w0; a3 += r3v.y * w1; a3 += r3v.z * w2; a3 += r3v.w * w3;
        }
        float av[4] = {a0, a1, a2, a3};
#pragma unroll
        for (int rr = 0; rr < 4; ++rr) {
            float vs = av[rr] * ash[tid];
            float vd = av[rr] * adh[tid];
#pragma unroll
            for (int off = 16; off; off >>= 1) {
                vs += __shfl_down_sync(0xffffffffu, vs, off);
                vd += __shfl_down_sync(0xffffffffu, vd, off);
            }
            if (lane == 0) { red[warp][rr][0] = vs; red[warp][rr][1] = vd; }
            int row = rowBase + r0 + rr;
            if (row < NN)
                g_hgh[(size_t)row * F2 + colOff + tid] = __float2half(av[rr]);
        }
        __syncthreads();
        if (tid < 16) {                     // rr(2b) | hl(1b) | sd(1b)
            int rr = tid & 3, hl = (tid >> 2) & 1, sd = tid >> 3;
            int row = rowBase + r0 + rr;
            if (row < NN) {
                float v = red[2 * hl][rr][sd] + red[2 * hl + 1][rr][sd];
                int head = (colOff >> 6) + hl;
                (sd ? g_ad : g_as)[row * HEADS + head] = v;
            }
        }
        __syncthreads();
    }
}

__device__ __forceinline__ float lrelu(float e) {
    return (e > 0.f) ? e : 0.2f * e;
}

// ---------------- GAT aggregation: warp per dst, online softmax (R3) --------
__global__ void gat_agg_kernel(const float* __restrict__ b_gat) {
    int gt   = blockIdx.x * blockDim.x + threadIdx.x;
    int warp = gt >> 5;
    if (warp >= NN) return;
    int lane = gt & 31;
    int hd   = lane >> 3;                   // head for this lane
    int base = hd * HID + (lane & 7) * 8;   // 8 contiguous features
    float adv = g_ad[warp * HEADS + hd];
    int beg = g_rowptr[warp], end = g_rowptr[warp + 1];
    float m = -3.0e38f, s = 0.f;
    float acc[8];
#pragma unroll
    for (int k = 0; k < 8; ++k) acc[k] = 0.f;

    int j = beg;
    for (; j + 2 <= end; j += 2) {
        int s0 = g_csr[j], s1 = g_csr[j + 1];
        float e0 = lrelu(g_as[s0 * HEADS + hd] + adv);
        float e1 = lrelu(g_as[s1 * HEADS + hd] + adv);
        int4 p0 = *(const int4*)(g_hgh + (size_t)s0 * F2 + base);
        int4 p1 = *(const int4*)(g_hgh + (size_t)s1 * F2 + base);
        float nm = fmaxf(m, fmaxf(e0, e1));
        float sc = __expf(m - nm);
        float w0 = __expf(e0 - nm);
        float w1 = __expf(e1 - nm);
        s = s * sc + w0 + w1;
        const __half2* h0 = (const __half2*)&p0;
        const __half2* h1 = (const __half2*)&p1;
#pragma unroll
        for (int k = 0; k < 4; ++k) {
            float2 a = __half22float2(h0[k]);
            float2 b = __half22float2(h1[k]);
            acc[2 * k]     = acc[2 * k]     * sc + w0 * a.x + w1 * b.x;
            acc[2 * k + 1] = acc[2 * k + 1] * sc + w0 * a.y + w1 * b.y;
        }
        m = nm;
    }
    if (j < end) {
        int s0 = g_csr[j];
        float e0 = lrelu(g_as[s0 * HEADS + hd] + adv);
        int4 p0 = *(const int4*)(g_hgh + (size_t)s0 * F2 + base);
        float nm = fmaxf(m, e0);
        float sc = __expf(m - nm);
        float w0 = __expf(e0 - nm);
        s = s * sc + w0;
        const __half2* h0 = (const __half2*)&p0;
#pragma unroll
        for (int k = 0; k < 4; ++k) {
            float2 a = __half22float2(h0[k]);
            acc[2 * k]     = acc[2 * k]     * sc + w0 * a.x;
            acc[2 * k + 1] = acc[2 * k + 1] * sc + w0 * a.y;
        }
    }
    float inv = 1.f / s;
    __half2* o = (__half2*)(g_out2h + (size_t)warp * F2 + base);
#pragma unroll
    for (int k = 0; k < 4; ++k) {
        float vx = fmaxf(acc[2 * k]     * inv + b_gat[base + 2 * k],     0.f);
        float vy = fmaxf(acc[2 * k + 1] * inv + b_gat[base + 2 * k + 1], 0.f);
        o[k] = __floats2half2_rn(vx, vy);
    }
}

// ---------------- GEMM 3: out = out2h @ W_fc + b_fc (50000x256 @ 256x32) ----
__global__ void gemm3_kernel(const float* __restrict__ Wfc,
                             const float* __restrict__ bfc,
                             float* __restrict__ out) {
    __shared__ float  Wsh[F2 * DOUT];       // 32 KB, layout [k][c]
    __shared__ __half insh[32 * F2];        // 16 KB, 32 rows
    int tid = threadIdx.x;                  // 256
    for (int q = tid; q < F2 * DOUT; q += 256) Wsh[q] = Wfc[q];
    int c  = tid & 31;
    int r4 = tid >> 5;                      // 0..7 -> rows r4*4..r4*4+3
    float bv = bfc[c];
    int rowBase = blockIdx.x * 128;
    for (int g = 0; g < 128; g += 32) {
        __syncthreads();
        for (int q = tid; q < 32 * 128; q += 256) {
            int rr = q >> 7, kk2 = q & 127;
            int row = rowBase + g + rr;
            ((__half2*)insh)[q] = (row < NN)
                ? ((const __half2*)(g_out2h + (size_t)row * F2))[kk2]
                : __floats2half2_rn(0.f, 0.f);
        }
        __syncthreads();
        float acc0 = 0.f, acc1 = 0.f, acc2 = 0.f, acc3 = 0.f;
        const uint2* in0 = (const uint2*)(insh + (r4 * 4 + 0) * F2);
        const uint2* in1 = (const uint2*)(insh + (r4 * 4 + 1) * F2);
        const uint2* in2 = (const uint2*)(insh + (r4 * 4 + 2) * F2);
        const uint2* in3 = (const uint2*)(insh + (r4 * 4 + 3) * F2);
#pragma unroll 8
        for (int k4 = 0; k4 < 64; ++k4) {
            uint2 u0 = in0[k4], u1 = in1[k4], u2 = in2[k4], u3 = in3[k4];
            float w0 = Wsh[(4 * k4 + 0) * DOUT + c];
            float w1 = Wsh[(4 * k4 + 1) * DOUT + c];
            float w2 = Wsh[(4 * k4 + 2) * DOUT + c];
            float w3 = Wsh[(4 * k4 + 3) * DOUT + c];
            float2 a0 = __half22float2(*(const __half2*)&u0.x);
            float2 b0 = __half22float2(*(const __half2*)&u0.y);
            float2 a1 = __half22float2(*(const __half2*)&u1.x);
            float2 b1 = __half22float2(*(const __half2*)&u1.y);
            float2 a2 = __half22float2(*(const __half2*)&u2.x);
            float2 b2 = __half22float2(*(const __half2*)&u2.y);
            float2 a3 = __half22float2(*(const __half2*)&u3.x);
            float2 b3 = __half22float2(*(const __half2*)&u3.y);
            acc0 += a0.x * w0 + a0.y * w1 + b0.x * w2 + b0.y * w3;
            acc1 += a1.x * w0 + a1.y * w1 + b1.x * w2 + b1.y * w3;
            acc2 += a2.x * w0 + a2.y * w1 + b2.x * w2 + b2.y * w3;
            acc3 += a3.x * w0 + a3.y * w1 + b3.x * w2 + b3.y * w3;
        }
        int row = rowBase + g + r4 * 4;
        if (row     < NN) out[(row    ) * DOUT + c] = acc0 + bv;
        if (row + 1 < NN) out[(row + 1) * DOUT + c] = acc1 + bv;
        if (row + 2 < NN) out[(row + 2) * DOUT + c] = acc2 + bv;
        if (row + 3 < NN) out[(row + 3) * DOUT + c] = acc3 + bv;
    }
}

// ---------------- launch ----------------------------------------------------
extern "C" void kernel_launch(void* const* d_in, const int* in_sizes, int n_in,
                              void* d_out, int out_size) {
    const float* x       = (const float*)d_in[0];
    const int*   ei      = (const int*)  d_in[1];   // int32 (JAX x64 off)
    const float* W_gcn   = (const float*)d_in[2];
    const float* b_gcn   = (const float*)d_in[3];
    const float* W_gat   = (const float*)d_in[4];
    const float* att_src = (const float*)d_in[5];
    const float* att_dst = (const float*)d_in[6];
    const float* b_gat   = (const float*)d_in[7];
    const float* W_fc    = (const float*)d_in[8];
    const float* b_fc    = (const float*)d_in[9];
    float*       out     = (float*)d_out;

    init_kernel        <<<(NN + 255) / 256, 256>>>();
    deg_kernel         <<<(EE + 255) / 256, 256>>>(ei);
    scan_partial_kernel<<<NB, 256>>>();
    rowptr_kernel      <<<NB, 256>>>();
    csr_fill_kernel    <<<(ET + 255) / 256, 256>>>(ei);

    gemm1_kernel       <<<(NN * 32 + 255) / 256, 256>>>(x, W_gcn);
    gcn_agg_kernel     <<<(NN * 32 + 255) / 256, 256>>>(b_gcn);

    gemm2_kernel       <<<dim3((NN + 63) / 64, 2), 128>>>(W_gat, att_src, att_dst);
    gat_agg_kernel     <<<(NN * 32 + 255) / 256, 256>>>(b_gat);

    gemm3_kernel       <<<(NN + 127) / 128, 256>>>(W_fc, b_fc, out);
}

// round 15
// speedup vs baseline: 1.1305x; 1.0625x over previous
#include <cuda_runtime.h>
#include <cuda_fp16.h>

// Problem constants (fixed by the dataset)
constexpr int NN   = 50000;
constexpr int EE   = 1600000;
constexpr int ET   = EE + NN;     // edges + self loops
constexpr int DIN  = 32;
constexpr int HID  = 64;
constexpr int HEADS= 4;
constexpr int F2   = HEADS * HID; // 256
constexpr int DOUT = 32;
constexpr int NB   = (NN + 255) / 256;   // 196 blocks for scan

// ---------------- scratch (device globals; no allocation allowed) -----------
__device__ __half g_hx  [NN * HID];  // (x @ W_gcn) * dinv[row]  (half)
__device__ float  g_h1  [NN * HID];  // relu(gcn)
__device__ __half g_hgh [NN * F2];   // h1 @ W_gat (half gather table)
__device__ __half g_out2h[NN * F2];  // relu(gat), half
__device__ float  g_as  [NN * HEADS];
__device__ float  g_ad  [NN * HEADS];
__device__ float  g_dinv[NN];
__device__ int    g_deg [NN];
__device__ int    g_rowptr[NN + 1];
__device__ int    g_bsum[NB];
__device__ int    g_pos [EE];        // position of edge within its dst row
__device__ int    g_csr [ET];

// ---------------- CSR build -------------------------------------------------
__global__ void deg_kernel(const int* __restrict__ ei) {
    int i = blockIdx.x * blockDim.x + threadIdx.x;
    if (i >= EE) return;
    int d = ei[EE + i];
    d = min(max(d, 0), NN - 1);
    g_pos[i] = atomicAdd(&g_deg[d], 1);    // position within row; no 2nd atomic later
}

// block partial sums of (deg+1)
__global__ void scan_partial_kernel() {
    __shared__ int sh[256];
    int t = threadIdx.x, b = blockIdx.x;
    int i = b * 256 + t;
    int v = (i < NN) ? g_deg[i] + 1 : 0;
    sh[t] = v;
    __syncthreads();
#pragma unroll
    for (int off = 128; off > 0; off >>= 1) {
        if (t < off) sh[t] += sh[t + off];
        __syncthreads();
    }
    if (t == 0) g_bsum[b] = sh[0];
}

// rowptr: block offset = reduction of g_bsum[0..b-1], then local scan
__global__ void rowptr_kernel() {
    __shared__ int sh[256];
    __shared__ int boff_sh;
    int t = threadIdx.x, b = blockIdx.x;
    int v0 = (t < b && t < NB) ? g_bsum[t] : 0;
    sh[t] = v0;
    __syncthreads();
#pragma unroll
    for (int off = 128; off > 0; off >>= 1) {
        if (t < off) sh[t] += sh[t + off];
        __syncthreads();
    }
    if (t == 0) boff_sh = sh[0];
    __syncthreads();
    int i = b * 256 + t;
    int v = (i < NN) ? g_deg[i] + 1 : 0;
    sh[t] = v;
    __syncthreads();
    for (int off = 1; off < 256; off <<= 1) {
        int u = (t >= off) ? sh[t - off] : 0;
        __syncthreads();
        sh[t] += u;
        __syncthreads();
    }
    int excl = sh[t] - v + boff_sh;
    if (i < NN) {
        g_rowptr[i] = excl;
        g_dinv[i] = rsqrtf((float)v);
        if (i == NN - 1) g_rowptr[NN] = excl + v;
    }
}

// plain scatter: edge -> rowptr[dst]+pos ; self-loop at rowptr[dst+1]-1
__global__ void csr_fill_kernel(const int* __restrict__ ei) {
    int i = blockIdx.x * blockDim.x + threadIdx.x;
    if (i >= ET) return;
    if (i < EE) {
        int src = min(max(ei[i], 0), NN - 1);
        int dst = min(max(ei[EE + i], 0), NN - 1);
        g_csr[g_rowptr[dst] + g_pos[i]] = src;
    } else {
        int node = i - EE;
        g_csr[g_rowptr[node + 1] - 1] = node;
    }
}

// ---------------- GEMM 1: hx = (x @ W_gcn) * dinv[row], half out ------------
__global__ void gemm1_kernel(const float* __restrict__ x,
                             const float* __restrict__ W) {
    __shared__ float Wsh[DIN * HID];        // 8 KB
    for (int i = threadIdx.x; i < DIN * HID; i += blockDim.x) Wsh[i] = W[i];
    __syncthreads();
    int gt   = blockIdx.x * blockDim.x + threadIdx.x;
    int warp = gt >> 5;
    int lane = gt & 31;
    if (warp >= NN) return;
    float xv = x[warp * DIN + lane];
    float a0 = 0.f, a1 = 0.f;
#pragma unroll
    for (int k = 0; k < 32; ++k) {
        float xk = __shfl_sync(0xffffffffu, xv, k);
        a0 += xk * Wsh[k * HID + lane];
        a1 += xk * Wsh[k * HID + 32 + lane];
    }
    float dv = g_dinv[warp];                // fold src-side norm into table
    g_hx[warp * HID + lane]      = __float2half(a0 * dv);
    g_hx[warp * HID + 32 + lane] = __float2half(a1 * dv);
}

// ---------------- GCN aggregation: warp per dst; no per-edge dinv gather ----
__global__ void gcn_agg_kernel(const float* __restrict__ b_gcn) {
    int gt   = blockIdx.x * blockDim.x + threadIdx.x;
    int warp = gt >> 5;
    if (warp >= NN) return;
    int lane = gt & 31;
    int beg = g_rowptr[warp], end = g_rowptr[warp + 1];
    float ax = 0.f, ay = 0.f;
    const __half2* hx2 = (const __half2*)g_hx;
    int j = beg;
    for (; j + 2 <= end; j += 2) {
        int s0 = g_csr[j], s1 = g_csr[j + 1];
        float2 a = __half22float2(hx2[s0 * 32 + lane]);
        float2 b = __half22float2(hx2[s1 * 32 + lane]);
        ax += a.x + b.x;
        ay += a.y + b.y;
    }
    if (j < end) {
        int s0 = g_csr[j];
        float2 a = __half22float2(hx2[s0 * 32 + lane]);
        ax += a.x;
        ay += a.y;
    }
    float dd = g_dinv[warp];                // dst-side norm applied once
    float2 o;
    o.x = fmaxf(ax * dd + b_gcn[2 * lane],     0.f);
    o.y = fmaxf(ay * dd + b_gcn[2 * lane + 1], 0.f);
    ((float2*)(g_h1 + (size_t)warp * HID))[lane] = o;
}

// ---------------- GEMM 2 + block-local attention dots (no atomics) ----------
__global__ void gemm2_kernel(const float* __restrict__ Wg,
                             const float* __restrict__ att_src,
                             const float* __restrict__ att_dst) {
    __shared__ float Wsh[64 * 128];         // 32 KB (half the columns)
    __shared__ float rsh[4 * 64];
    __shared__ float ash[128], adh[128];
    __shared__ float red[4][4][2];          // [warp][row][s|d]
    int tid = threadIdx.x;                  // 128
    int colOff = blockIdx.y * 128;
    ash[tid] = att_src[colOff + tid];
    adh[tid] = att_dst[colOff + tid];
    for (int q = tid; q < 64 * 128; q += 128) {
        int k = q >> 7, c = q & 127;
        Wsh[q] = Wg[k * F2 + colOff + c];
    }
    __syncthreads();
    int lane = tid & 31, warp = tid >> 5;
    int rowBase = blockIdx.x * 64;
    for (int r0 = 0; r0 < 64; r0 += 4) {
        for (int q = tid; q < 256; q += 128) {
            int rr = q >> 6, kk = q & 63;
            int row = rowBase + r0 + rr;
            rsh[q] = (row < NN) ? g_h1[(size_t)row * HID + kk] : 0.f;
        }
        __syncthreads();
        float a0 = 0.f, a1 = 0.f, a2 = 0.f, a3 = 0.f;
#pragma unroll
        for (int k = 0; k < 64; ++k) {
            float w = Wsh[k * 128 + tid];
            a0 += rsh[k]       * w;
            a1 += rsh[64 + k]  * w;
            a2 += rsh[128 + k] * w;
            a3 += rsh[192 + k] * w;
        }
        float av[4] = {a0, a1, a2, a3};
#pragma unroll
        for (int rr = 0; rr < 4; ++rr) {
            float vs = av[rr] * ash[tid];
            float vd = av[rr] * adh[tid];
#pragma unroll
            for (int off = 16; off; off >>= 1) {
                vs += __shfl_down_sync(0xffffffffu, vs, off);
                vd += __shfl_down_sync(0xffffffffu, vd, off);
            }
            if (lane == 0) { red[warp][rr][0] = vs; red[warp][rr][1] = vd; }
            int row = rowBase + r0 + rr;
            if (row < NN)
                g_hgh[(size_t)row * F2 + colOff + tid] = __float2half(av[rr]);
        }
        __syncthreads();
        if (tid < 16) {                     // rr(2b) | hl(1b) | sd(1b)
            int rr = tid & 3, hl = (tid >> 2) & 1, sd = tid >> 3;
            int row = rowBase + r0 + rr;
            if (row < NN) {
                float v = red[2 * hl][rr][sd] + red[2 * hl + 1][rr][sd];
                int head = (colOff >> 6) + hl;
                (sd ? g_ad : g_as)[row * HEADS + head] = v;
            }
        }
        __syncthreads();
    }
}

__device__ __forceinline__ float lrelu(float e) {
    return (e > 0.f) ? e : 0.2f * e;
}

// ---------------- GAT aggregation: warp per dst, online softmax (R3) --------
__global__ void gat_agg_kernel(const float* __restrict__ b_gat) {
    int gt   = blockIdx.x * blockDim.x + threadIdx.x;
    int warp = gt >> 5;
    if (warp >= NN) return;
    int lane = gt & 31;
    int hd   = lane >> 3;                   // head for this lane
    int base = hd * HID + (lane & 7) * 8;   // 8 contiguous features
    float adv = g_ad[warp * HEADS + hd];
    int beg = g_rowptr[warp], end = g_rowptr[warp + 1];
    float m = -3.0e38f, s = 0.f;
    float acc[8];
#pragma unroll
    for (int k = 0; k < 8; ++k) acc[k] = 0.f;

    int j = beg;
    for (; j + 2 <= end; j += 2) {
        int s0 = g_csr[j], s1 = g_csr[j + 1];
        float e0 = lrelu(g_as[s0 * HEADS + hd] + adv);
        float e1 = lrelu(g_as[s1 * HEADS + hd] + adv);
        int4 p0 = *(const int4*)(g_hgh + (size_t)s0 * F2 + base);
        int4 p1 = *(const int4*)(g_hgh + (size_t)s1 * F2 + base);
        float nm = fmaxf(m, fmaxf(e0, e1));
        float sc = __expf(m - nm);
        float w0 = __expf(e0 - nm);
        float w1 = __expf(e1 - nm);
        s = s * sc + w0 + w1;
        const __half2* h0 = (const __half2*)&p0;
        const __half2* h1 = (const __half2*)&p1;
#pragma unroll
        for (int k = 0; k < 4; ++k) {
            float2 a = __half22float2(h0[k]);
            float2 b = __half22float2(h1[k]);
            acc[2 * k]     = acc[2 * k]     * sc + w0 * a.x + w1 * b.x;
            acc[2 * k + 1] = acc[2 * k + 1] * sc + w0 * a.y + w1 * b.y;
        }
        m = nm;
    }
    if (j < end) {
        int s0 = g_csr[j];
        float e0 = lrelu(g_as[s0 * HEADS + hd] + adv);
        int4 p0 = *(const int4*)(g_hgh + (size_t)s0 * F2 + base);
        float nm = fmaxf(m, e0);
        float sc = __expf(m - nm);
        float w0 = __expf(e0 - nm);
        s = s * sc + w0;
        const __half2* h0 = (const __half2*)&p0;
#pragma unroll
        for (int k = 0; k < 4; ++k) {
            float2 a = __half22float2(h0[k]);
            acc[2 * k]     = acc[2 * k]     * sc + w0 * a.x;
            acc[2 * k + 1] = acc[2 * k + 1] * sc + w0 * a.y;
        }
    }
    float inv = 1.f / s;
    __half2* o = (__half2*)(g_out2h + (size_t)warp * F2 + base);
#pragma unroll
    for (int k = 0; k < 4; ++k) {
        float vx = fmaxf(acc[2 * k]     * inv + b_gat[base + 2 * k],     0.f);
        float vy = fmaxf(acc[2 * k + 1] * inv + b_gat[base + 2 * k + 1], 0.f);
        o[k] = __floats2half2_rn(vx, vy);
    }
}

// ---------------- GEMM 3: out = out2h @ W_fc + b_fc (50000x256 @ 256x32) ----
__global__ void gemm3_kernel(const float* __restrict__ Wfc,
                             const float* __restrict__ bfc,
                             float* __restrict__ out) {
    __shared__ float  Wsh[F2 * DOUT];       // 32 KB, layout [k][c]
    __shared__ __half insh[32 * F2];        // 16 KB, 32 rows
    int tid = threadIdx.x;                  // 256
    for (int q = tid; q < F2 * DOUT; q += 256) Wsh[q] = Wfc[q];
    int c  = tid & 31;
    int r4 = tid >> 5;                      // 0..7 -> rows r4*4..r4*4+3
    float bv = bfc[c];
    int rowBase = blockIdx.x * 128;
    for (int g = 0; g < 128; g += 32) {
        __syncthreads();
        for (int q = tid; q < 32 * 128; q += 256) {
            int rr = q >> 7, kk2 = q & 127;
            int row = rowBase + g + rr;
            ((__half2*)insh)[q] = (row < NN)
                ? ((const __half2*)(g_out2h + (size_t)row * F2))[kk2]
                : __floats2half2_rn(0.f, 0.f);
        }
        __syncthreads();
        float acc0 = 0.f, acc1 = 0.f, acc2 = 0.f, acc3 = 0.f;
        const uint2* in0 = (const uint2*)(insh + (r4 * 4 + 0) * F2);
        const uint2* in1 = (const uint2*)(insh + (r4 * 4 + 1) * F2);
        const uint2* in2 = (const uint2*)(insh + (r4 * 4 + 2) * F2);
        const uint2* in3 = (const uint2*)(insh + (r4 * 4 + 3) * F2);
#pragma unroll 8
        for (int k4 = 0; k4 < 64; ++k4) {
            uint2 u0 = in0[k4], u1 = in1[k4], u2 = in2[k4], u3 = in3[k4];
            float w0 = Wsh[(4 * k4 + 0) * DOUT + c];
            float w1 = Wsh[(4 * k4 + 1) * DOUT + c];
            float w2 = Wsh[(4 * k4 + 2) * DOUT + c];
            float w3 = Wsh[(4 * k4 + 3) * DOUT + c];
            float2 a0 = __half22float2(*(const __half2*)&u0.x);
            float2 b0 = __half22float2(*(const __half2*)&u0.y);
            float2 a1 = __half22float2(*(const __half2*)&u1.x);
            float2 b1 = __half22float2(*(const __half2*)&u1.y);
            float2 a2 = __half22float2(*(const __half2*)&u2.x);
            float2 b2 = __half22float2(*(const __half2*)&u2.y);
            float2 a3 = __half22float2(*(const __half2*)&u3.x);
            float2 b3 = __half22float2(*(const __half2*)&u3.y);
            acc0 += a0.x * w0 + a0.y * w1 + b0.x * w2 + b0.y * w3;
            acc1 += a1.x * w0 + a1.y * w1 + b1.x * w2 + b1.y * w3;
            acc2 += a2.x * w0 + a2.y * w1 + b2.x * w2 + b2.y * w3;
            acc3 += a3.x * w0 + a3.y * w1 + b3.x * w2 + b3.y * w3;
        }
        int row = rowBase + g + r4 * 4;
        if (row     < NN) out[(row    ) * DOUT + c] = acc0 + bv;
        if (row + 1 < NN) out[(row + 1) * DOUT + c] = acc1 + bv;
        if (row + 2 < NN) out[(row + 2) * DOUT + c] = acc2 + bv;
        if (row + 3 < NN) out[(row + 3) * DOUT + c] = acc3 + bv;
    }
}

// ---------------- launch ----------------------------------------------------
extern "C" void kernel_launch(void* const* d_in, const int* in_sizes, int n_in,
                              void* d_out, int out_size) {
    const float* x       = (const float*)d_in[0];
    const int*   ei      = (const int*)  d_in[1];   // int32 (JAX x64 off)
    const float* W_gcn   = (const float*)d_in[2];
    const float* b_gcn   = (const float*)d_in[3];
    const float* W_gat   = (const float*)d_in[4];
    const float* att_src = (const float*)d_in[5];
    const float* att_dst = (const float*)d_in[6];
    const float* b_gat   = (const float*)d_in[7];
    const float* W_fc    = (const float*)d_in[8];
    const float* b_fc    = (const float*)d_in[9];
    float*       out     = (float*)d_out;

    void* degPtr = nullptr;
    cudaGetSymbolAddress(&degPtr, g_deg);
    cudaMemsetAsync(degPtr, 0, NN * sizeof(int));   // graph-capturable memset

    deg_kernel         <<<(EE + 255) / 256, 256>>>(ei);
    scan_partial_kernel<<<NB, 256>>>();
    rowptr_kernel      <<<NB, 256>>>();
    csr_fill_kernel    <<<(ET + 255) / 256, 256>>>(ei);

    gemm1_kernel       <<<(NN * 32 + 255) / 256, 256>>>(x, W_gcn);
    gcn_agg_kernel     <<<(NN * 32 + 255) / 256, 256>>>(b_gcn);

    gemm2_kernel       <<<dim3((NN + 63) / 64, 2), 128>>>(W_gat, att_src, att_dst);
    gat_agg_kernel     <<<(NN * 32 + 255) / 256, 256>>>(b_gat);

    gemm3_kernel       <<<(NN + 127) / 128, 256>>>(W_fc, b_fc, out);
}

// round 17
// speedup vs baseline: 1.4511x; 1.2836x over previous
#include <cuda_runtime.h>
#include <cuda_fp16.h>
#include <cstdint>

// Problem constants (fixed by the dataset)
constexpr int NN   = 50000;
constexpr int EE   = 1600000;
constexpr int ET   = EE + NN;     // edges + self loops
constexpr int DIN  = 32;
constexpr int HID  = 64;
constexpr int HEADS= 4;
constexpr int F2   = HEADS * HID; // 256
constexpr int DOUT = 32;
constexpr int NB   = (NN + 255) / 256;   // 196 blocks for scan
constexpr int PADK = 72;                 // padded k-stride (halves) for mma smem

// ---------------- scratch (device globals; no allocation allowed) -----------
__device__ __half g_hx  [NN * HID];  // (x @ W_gcn) * dinv[row]  (half)
__device__ float  g_h1  [NN * HID];  // relu(gcn)
__device__ __half g_hgh [NN * F2];   // h1 @ W_gat (half gather table)
__device__ __half g_out2h[NN * F2];  // relu(gat), half
__device__ float  g_as  [NN * HEADS];
__device__ float  g_ad  [NN * HEADS];
__device__ float  g_dinv[NN];
__device__ int    g_deg [NN];
__device__ int    g_rowptr[NN + 1];
__device__ int    g_bsum[NB];
__device__ int    g_pos [EE];        // position of edge within its dst row
__device__ int    g_csr [ET];

// ---------------- CSR build -------------------------------------------------
__global__ void deg_kernel(const int* __restrict__ ei) {
    int i = blockIdx.x * blockDim.x + threadIdx.x;
    if (i >= EE) return;
    int d = ei[EE + i];
    d = min(max(d, 0), NN - 1);
    g_pos[i] = atomicAdd(&g_deg[d], 1);    // position within row; no 2nd atomic later
}

// block partial sums of (deg+1)
__global__ void scan_partial_kernel() {
    __shared__ int sh[256];
    int t = threadIdx.x, b = blockIdx.x;
    int i = b * 256 + t;
    int v = (i < NN) ? g_deg[i] + 1 : 0;
    sh[t] = v;
    __syncthreads();
#pragma unroll
    for (int off = 128; off > 0; off >>= 1) {
        if (t < off) sh[t] += sh[t + off];
        __syncthreads();
    }
    if (t == 0) g_bsum[b] = sh[0];
}

// rowptr: block offset = reduction of g_bsum[0..b-1], then local scan
__global__ void rowptr_kernel() {
    __shared__ int sh[256];
    __shared__ int boff_sh;
    int t = threadIdx.x, b = blockIdx.x;
    int v0 = (t < b && t < NB) ? g_bsum[t] : 0;
    sh[t] = v0;
    __syncthreads();
#pragma unroll
    for (int off = 128; off > 0; off >>= 1) {
        if (t < off) sh[t] += sh[t + off];
        __syncthreads();
    }
    if (t == 0) boff_sh = sh[0];
    __syncthreads();
    int i = b * 256 + t;
    int v = (i < NN) ? g_deg[i] + 1 : 0;
    sh[t] = v;
    __syncthreads();
    for (int off = 1; off < 256; off <<= 1) {
        int u = (t >= off) ? sh[t - off] : 0;
        __syncthreads();
        sh[t] += u;
        __syncthreads();
    }
    int excl = sh[t] - v + boff_sh;
    if (i < NN) {
        g_rowptr[i] = excl;
        g_dinv[i] = rsqrtf((float)v);
        if (i == NN - 1) g_rowptr[NN] = excl + v;
    }
}

// plain scatter: edge -> rowptr[dst]+pos ; self-loop at rowptr[dst+1]-1
__global__ void csr_fill_kernel(const int* __restrict__ ei) {
    int i = blockIdx.x * blockDim.x + threadIdx.x;
    if (i >= ET) return;
    if (i < EE) {
        int src = min(max(ei[i], 0), NN - 1);
        int dst = min(max(ei[EE + i], 0), NN - 1);
        g_csr[g_rowptr[dst] + g_pos[i]] = src;
    } else {
        int node = i - EE;
        g_csr[g_rowptr[node + 1] - 1] = node;
    }
}

// ---------------- GEMM 1: hx = (x @ W_gcn) * dinv[row], half out ------------
__global__ void gemm1_kernel(const float* __restrict__ x,
                             const float* __restrict__ W) {
    __shared__ float Wsh[DIN * HID];        // 8 KB
    for (int i = threadIdx.x; i < DIN * HID; i += blockDim.x) Wsh[i] = W[i];
    __syncthreads();
    int gt   = blockIdx.x * blockDim.x + threadIdx.x;
    int warp = gt >> 5;
    int lane = gt & 31;
    if (warp >= NN) return;
    float xv = x[warp * DIN + lane];
    float a0 = 0.f, a1 = 0.f;
#pragma unroll
    for (int k = 0; k < 32; ++k) {
        float xk = __shfl_sync(0xffffffffu, xv, k);
        a0 += xk * Wsh[k * HID + lane];
        a1 += xk * Wsh[k * HID + 32 + lane];
    }
    float dv = g_dinv[warp];                // fold src-side norm into table
    g_hx[warp * HID + lane]      = __float2half(a0 * dv);
    g_hx[warp * HID + 32 + lane] = __float2half(a1 * dv);
}

// ---------------- GCN aggregation: warp per dst; no per-edge dinv gather ----
__global__ void gcn_agg_kernel(const float* __restrict__ b_gcn) {
    int gt   = blockIdx.x * blockDim.x + threadIdx.x;
    int warp = gt >> 5;
    if (warp >= NN) return;
    int lane = gt & 31;
    int beg = g_rowptr[warp], end = g_rowptr[warp + 1];
    float ax = 0.f, ay = 0.f;
    const __half2* hx2 = (const __half2*)g_hx;
    int j = beg;
    for (; j + 2 <= end; j += 2) {
        int s0 = g_csr[j], s1 = g_csr[j + 1];
        float2 a = __half22float2(hx2[s0 * 32 + lane]);
        float2 b = __half22float2(hx2[s1 * 32 + lane]);
        ax += a.x + b.x;
        ay += a.y + b.y;
    }
    if (j < end) {
        int s0 = g_csr[j];
        float2 a = __half22float2(hx2[s0 * 32 + lane]);
        ax += a.x;
        ay += a.y;
    }
    float dd = g_dinv[warp];                // dst-side norm applied once
    float2 o;
    o.x = fmaxf(ax * dd + b_gcn[2 * lane],     0.f);
    o.y = fmaxf(ay * dd + b_gcn[2 * lane + 1], 0.f);
    ((float2*)(g_h1 + (size_t)warp * HID))[lane] = o;
}

// ---------------- GEMM 2 via HMMA (m16n8k16) + in-warp attention dots -------
// D[64, 128] = A[64, 64] @ W[64, 128] per block (blockIdx.y picks col half).
// 8 warps: warp (w&3) -> 16-row group, (w>>2) -> 64-col group (= one head).
__global__ void gemm2_kernel(const float* __restrict__ Wg,
                             const float* __restrict__ att_src,
                             const float* __restrict__ att_dst) {
    __shared__ __half Ash[64 * PADK];       // 9.2 KB
    __shared__ __half Bsh[128 * PADK];      // 18.4 KB, Bsh[n][k] = W[k][colOff+n]
    __shared__ float  ash[128], adh[128];
    int tid = threadIdx.x;                  // 256
    int colOff = blockIdx.y * 128;
    if (tid < 128) {
        ash[tid] = att_src[colOff + tid];
        adh[tid] = att_dst[colOff + tid];
    }
    int rowBase = blockIdx.x * 64;
    // A tile: 64 rows x 64 fp32 -> half (zero-pad OOB rows)
    for (int q = tid; q < 64 * 64; q += 256) {
        int r = q >> 6, k = q & 63;
        int row = rowBase + r;
        float v = (row < NN) ? g_h1[(size_t)row * HID + k] : 0.f;
        Ash[r * PADK + k] = __float2half(v);
    }
    // W transposed: coalesced global reads (consecutive n)
    for (int q = tid; q < 128 * 64; q += 256) {
        int k = q >> 7, n = q & 127;
        Bsh[n * PADK + k] = __float2half(Wg[k * F2 + colOff + n]);
    }
    __syncthreads();

    int w    = tid >> 5;
    int lane = tid & 31;
    int g    = lane >> 2;                   // group id
    int t    = lane & 3;                    // thread in group
    int rowGrp = (w & 3) * 16;
    int colGrp = (w >> 2) * 64;

    float acc[8][4];
#pragma unroll
    for (int nt = 0; nt < 8; ++nt)
#pragma unroll
        for (int q = 0; q < 4; ++q) acc[nt][q] = 0.f;

#pragma unroll
    for (int kk = 0; kk < 64; kk += 16) {
        uint32_t a0 = *(const uint32_t*)&Ash[(rowGrp + g    ) * PADK + kk + 2 * t    ];
        uint32_t a1 = *(const uint32_t*)&Ash[(rowGrp + g + 8) * PADK + kk + 2 * t    ];
        uint32_t a2 = *(const uint32_t*)&Ash[(rowGrp + g    ) * PADK + kk + 2 * t + 8];
        uint32_t a3 = *(const uint32_t*)&Ash[(rowGrp + g + 8) * PADK + kk + 2 * t + 8];
#pragma unroll
        for (int nt = 0; nt < 8; ++nt) {
            uint32_t b0 = *(const uint32_t*)&Bsh[(colGrp + nt * 8 + g) * PADK + kk + 2 * t    ];
            uint32_t b1 = *(const uint32_t*)&Bsh[(colGrp + nt * 8 + g) * PADK + kk + 2 * t + 8];
            asm volatile(
                "mma.sync.aligned.m16n8k16.row.col.f32.f16.f16.f32 "
                "{%0,%1,%2,%3},{%4,%5,%6,%7},{%8,%9},{%0,%1,%2,%3};"
                : "+f"(acc[nt][0]), "+f"(acc[nt][1]), "+f"(acc[nt][2]), "+f"(acc[nt][3])
                : "r"(a0), "r"(a1), "r"(a2), "r"(a3), "r"(b0), "r"(b1));
        }
    }

    // epilogue: store half table + per-head attention dots (in-warp)
    int r0 = rowBase + rowGrp + g;
    int r1 = r0 + 8;
    float ps0 = 0.f, pd0 = 0.f, ps1 = 0.f, pd1 = 0.f;
#pragma unroll
    for (int nt = 0; nt < 8; ++nt) {
        int lc = colGrp + nt * 8 + 2 * t;   // local col in [0,128)
        float sv0 = ash[lc], sv1 = ash[lc + 1];
        float dv0 = adh[lc], dv1 = adh[lc + 1];
        ps0 += acc[nt][0] * sv0 + acc[nt][1] * sv1;
        pd0 += acc[nt][0] * dv0 + acc[nt][1] * dv1;
        ps1 += acc[nt][2] * sv0 + acc[nt][3] * sv1;
        pd1 += acc[nt][2] * dv0 + acc[nt][3] * dv1;
        if (r0 < NN)
            *(__half2*)&g_hgh[(size_t)r0 * F2 + colOff + lc] =
                __floats2half2_rn(acc[nt][0], acc[nt][1]);
        if (r1 < NN)
            *(__half2*)&g_hgh[(size_t)r1 * F2 + colOff + lc] =
                __floats2half2_rn(acc[nt][2], acc[nt][3]);
    }
    // reduce over the 4 lanes of the quad (t = lane&3)
    ps0 += __shfl_xor_sync(0xffffffffu, ps0, 1);
    ps0 += __shfl_xor_sync(0xffffffffu, ps0, 2);
    pd0 += __shfl_xor_sync(0xffffffffu, pd0, 1);
    pd0 += __shfl_xor_sync(0xffffffffu, pd0, 2);
    ps1 += __shfl_xor_sync(0xffffffffu, ps1, 1);
    ps1 += __shfl_xor_sync(0xffffffffu, ps1, 2);
    pd1 += __shfl_xor_sync(0xffffffffu, pd1, 1);
    pd1 += __shfl_xor_sync(0xffffffffu, pd1, 2);
    if (t == 0) {
        int head = (colOff + colGrp) >> 6;
        if (r0 < NN) { g_as[r0 * HEADS + head] = ps0; g_ad[r0 * HEADS + head] = pd0; }
        if (r1 < NN) { g_as[r1 * HEADS + head] = ps1; g_ad[r1 * HEADS + head] = pd1; }
    }
}

__device__ __forceinline__ float lrelu(float e) {
    return (e > 0.f) ? e : 0.2f * e;
}

// ---------------- GAT aggregation: warp per dst, online softmax (R3) --------
__global__ void gat_agg_kernel(const float* __restrict__ b_gat) {
    int gt   = blockIdx.x * blockDim.x + threadIdx.x;
    int warp = gt >> 5;
    if (warp >= NN) return;
    int lane = gt & 31;
    int hd   = lane >> 3;                   // head for this lane
    int base = hd * HID + (lane & 7) * 8;   // 8 contiguous features
    float adv = g_ad[warp * HEADS + hd];
    int beg = g_rowptr[warp], end = g_rowptr[warp + 1];
    float m = -3.0e38f, s = 0.f;
    float acc[8];
#pragma unroll
    for (int k = 0; k < 8; ++k) acc[k] = 0.f;

    int j = beg;
    for (; j + 2 <= end; j += 2) {
        int s0 = g_csr[j], s1 = g_csr[j + 1];
        float e0 = lrelu(g_as[s0 * HEADS + hd] + adv);
        float e1 = lrelu(g_as[s1 * HEADS + hd] + adv);
        int4 p0 = *(const int4*)(g_hgh + (size_t)s0 * F2 + base);
        int4 p1 = *(const int4*)(g_hgh + (size_t)s1 * F2 + base);
        float nm = fmaxf(m, fmaxf(e0, e1));
        float sc = __expf(m - nm);
        float w0 = __expf(e0 - nm);
        float w1 = __expf(e1 - nm);
        s = s * sc + w0 + w1;
        const __half2* h0 = (const __half2*)&p0;
        const __half2* h1 = (const __half2*)&p1;
#pragma unroll
        for (int k = 0; k < 4; ++k) {
            float2 a = __half22float2(h0[k]);
            float2 b = __half22float2(h1[k]);
            acc[2 * k]     = acc[2 * k]     * sc + w0 * a.x + w1 * b.x;
            acc[2 * k + 1] = acc[2 * k + 1] * sc + w0 * a.y + w1 * b.y;
        }
        m = nm;
    }
    if (j < end) {
        int s0 = g_csr[j];
        float e0 = lrelu(g_as[s0 * HEADS + hd] + adv);
        int4 p0 = *(const int4*)(g_hgh + (size_t)s0 * F2 + base);
        float nm = fmaxf(m, e0);
        float sc = __expf(m - nm);
        float w0 = __expf(e0 - nm);
        s = s * sc + w0;
        const __half2* h0 = (const __half2*)&p0;
#pragma unroll
        for (int k = 0; k < 4; ++k) {
            float2 a = __half22float2(h0[k]);
            acc[2 * k]     = acc[2 * k]     * sc + w0 * a.x;
            acc[2 * k + 1] = acc[2 * k + 1] * sc + w0 * a.y;
        }
    }
    float inv = 1.f / s;
    __half2* o = (__half2*)(g_out2h + (size_t)warp * F2 + base);
#pragma unroll
    for (int k = 0; k < 4; ++k) {
        float vx = fmaxf(acc[2 * k]     * inv + b_gat[base + 2 * k],     0.f);
        float vy = fmaxf(acc[2 * k + 1] * inv + b_gat[base + 2 * k + 1], 0.f);
        o[k] = __floats2half2_rn(vx, vy);
    }
}

// ---------------- GEMM 3: out = out2h @ W_fc + b_fc (50000x256 @ 256x32) ----
__global__ void gemm3_kernel(const float* __restrict__ Wfc,
                             const float* __restrict__ bfc,
                             float* __restrict__ out) {
    __shared__ float  Wsh[F2 * DOUT];       // 32 KB, layout [k][c]
    __shared__ __half insh[32 * F2];        // 16 KB, 32 rows
    int tid = threadIdx.x;                  // 256
    for (int q = tid; q < F2 * DOUT; q += 256) Wsh[q] = Wfc[q];
    int c  = tid & 31;
    int r4 = tid >> 5;                      // 0..7 -> rows r4*4..r4*4+3
    float bv = bfc[c];
    int rowBase = blockIdx.x * 128;
    for (int g = 0; g < 128; g += 32) {
        __syncthreads();
        for (int q = tid; q < 32 * 128; q += 256) {
            int rr = q >> 7, kk2 = q & 127;
            int row = rowBase + g + rr;
            ((__half2*)insh)[q] = (row < NN)
                ? ((const __half2*)(g_out2h + (size_t)row * F2))[kk2]
                : __floats2half2_rn(0.f, 0.f);
        }
        __syncthreads();
        float acc0 = 0.f, acc1 = 0.f, acc2 = 0.f, acc3 = 0.f;
        const uint2* in0 = (const uint2*)(insh + (r4 * 4 + 0) * F2);
        const uint2* in1 = (const uint2*)(insh + (r4 * 4 + 1) * F2);
        const uint2* in2 = (const uint2*)(insh + (r4 * 4 + 2) * F2);
        const uint2* in3 = (const uint2*)(insh + (r4 * 4 + 3) * F2);
#pragma unroll 8
        for (int k4 = 0; k4 < 64; ++k4) {
            uint2 u0 = in0[k4], u1 = in1[k4], u2 = in2[k4], u3 = in3[k4];
            float w0 = Wsh[(4 * k4 + 0) * DOUT + c];
            float w1 = Wsh[(4 * k4 + 1) * DOUT + c];
            float w2 = Wsh[(4 * k4 + 2) * DOUT + c];
            float w3 = Wsh[(4 * k4 + 3) * DOUT + c];
            float2 a0 = __half22float2(*(const __half2*)&u0.x);
            float2 b0 = __half22float2(*(const __half2*)&u0.y);
            float2 a1 = __half22float2(*(const __half2*)&u1.x);
            float2 b1 = __half22float2(*(const __half2*)&u1.y);
            float2 a2 = __half22float2(*(const __half2*)&u2.x);
            float2 b2 = __half22float2(*(const __half2*)&u2.y);
            float2 a3 = __half22float2(*(const __half2*)&u3.x);
            float2 b3 = __half22float2(*(const __half2*)&u3.y);
            acc0 += a0.x * w0 + a0.y * w1 + b0.x * w2 + b0.y * w3;
            acc1 += a1.x * w0 + a1.y * w1 + b1.x * w2 + b1.y * w3;
            acc2 += a2.x * w0 + a2.y * w1 + b2.x * w2 + b2.y * w3;
            acc3 += a3.x * w0 + a3.y * w1 + b3.x * w2 + b3.y * w3;
        }
        int row = rowBase + g + r4 * 4;
        if (row     < NN) out[(row    ) * DOUT + c] = acc0 + bv;
        if (row + 1 < NN) out[(row + 1) * DOUT + c] = acc1 + bv;
        if (row + 2 < NN) out[(row + 2) * DOUT + c] = acc2 + bv;
        if (row + 3 < NN) out[(row + 3) * DOUT + c] = acc3 + bv;
    }
}

// ---------------- launch ----------------------------------------------------
extern "C" void kernel_launch(void* const* d_in, const int* in_sizes, int n_in,
                              void* d_out, int out_size) {
    const float* x       = (const float*)d_in[0];
    const int*   ei      = (const int*)  d_in[1];   // int32 (JAX x64 off)
    const float* W_gcn   = (const float*)d_in[2];
    const float* b_gcn   = (const float*)d_in[3];
    const float* W_gat   = (const float*)d_in[4];
    const float* att_src = (const float*)d_in[5];
    const float* att_dst = (const float*)d_in[6];
    const float* b_gat   = (const float*)d_in[7];
    const float* W_fc    = (const float*)d_in[8];
    const float* b_fc    = (const float*)d_in[9];
    float*       out     = (float*)d_out;

    void* degPtr = nullptr;
    cudaGetSymbolAddress(&degPtr, g_deg);
    cudaMemsetAsync(degPtr, 0, NN * sizeof(int));   // graph-capturable memset

    deg_kernel         <<<(EE + 255) / 256, 256>>>(ei);
    scan_partial_kernel<<<NB, 256>>>();
    rowptr_kernel      <<<NB, 256>>>();
    csr_fill_kernel    <<<(ET + 255) / 256, 256>>>(ei);

    gemm1_kernel       <<<(NN * 32 + 255) / 256, 256>>>(x, W_gcn);
    gcn_agg_kernel     <<<(NN * 32 + 255) / 256, 256>>>(b_gcn);

    gemm2_kernel       <<<dim3((NN + 63) / 64, 2), 256>>>(W_gat, att_src, att_dst);
    gat_agg_kernel     <<<(NN * 32 + 255) / 256, 256>>>(b_gat);

    gemm3_kernel       <<<(NN + 127) / 128, 256>>>(W_fc, b_fc, out);
}